// round 5
// baseline (speedup 1.0000x reference)
#include <cuda_runtime.h>
#include <cuda_bf16.h>
#include <cstdint>

#define HEADS 8
#define DH    64
#define NPIX  1024
#define CC    512
#define NB    8
#define NBH   64

typedef unsigned long long u64;

// ---- scratch: bf16 hi/lo split operands (allocation-guard-safe globals) ----
__device__ __align__(16) __nv_bfloat16 g_qh[NBH * NPIX * DH];  // [bh][n][d]
__device__ __align__(16) __nv_bfloat16 g_ql[NBH * NPIX * DH];
__device__ __align__(16) __nv_bfloat16 g_kh[NBH * NPIX * DH];
__device__ __align__(16) __nv_bfloat16 g_kl[NBH * NPIX * DH];
__device__ __align__(16) __nv_bfloat16 g_vh[NBH * NPIX * DH];  // [bh][n][d]
__device__ __align__(16) __nv_bfloat16 g_vl[NBH * NPIX * DH];
__device__ __align__(16) __nv_bfloat16 g_ph[HEADS * NPIX * DH]; // [h][n][d]
__device__ __align__(16) __nv_bfloat16 g_pl[HEADS * NPIX * DH];

// ---- packed f32x2 helpers (projection mainloop) ----
__device__ __forceinline__ void ffma2(u64 &c, u64 a, u64 b) {
    asm("fma.rn.f32x2 %0, %1, %2, %0;" : "+l"(c) : "l"(a), "l"(b));
}
__device__ __forceinline__ void unpack2(u64 v, float &x, float &y) {
    asm("mov.b64 {%0, %1}, %2;" : "=f"(x), "=f"(y) : "l"(v));
}
__device__ __forceinline__ void bsplit(float y, __nv_bfloat16 &hi, __nv_bfloat16 &lo) {
    hi = __float2bfloat16(y);
    lo = __float2bfloat16(y - __bfloat162float(hi));
}

// ---- mma.sync / ldmatrix primitives (baseline PTX, sm_80+) ----
__device__ __forceinline__ uint32_t smem_to_u32(const void *p) {
    uint32_t a;
    asm("{ .reg .u64 t; cvta.to.shared.u64 t, %1; cvt.u32.u64 %0, t; }"
        : "=r"(a) : "l"(p));
    return a;
}
__device__ __forceinline__ void ldsm4(uint32_t *r, uint32_t addr) {
    asm volatile("ldmatrix.sync.aligned.m8n8.x4.shared.b16 {%0,%1,%2,%3}, [%4];"
                 : "=r"(r[0]), "=r"(r[1]), "=r"(r[2]), "=r"(r[3]) : "r"(addr));
}
__device__ __forceinline__ void ldsm4t(uint32_t *r, uint32_t addr) {
    asm volatile("ldmatrix.sync.aligned.m8n8.x4.trans.shared.b16 {%0,%1,%2,%3}, [%4];"
                 : "=r"(r[0]), "=r"(r[1]), "=r"(r[2]), "=r"(r[3]) : "r"(addr));
}
__device__ __forceinline__ void hmma(float *c, const uint32_t *a, uint32_t b0, uint32_t b1) {
    asm volatile(
        "mma.sync.aligned.m16n8k16.row.col.f32.bf16.bf16.f32 "
        "{%0,%1,%2,%3}, {%4,%5,%6,%7}, {%8,%9}, {%0,%1,%2,%3};"
        : "+f"(c[0]), "+f"(c[1]), "+f"(c[2]), "+f"(c[3])
        : "r"(a[0]), "r"(a[1]), "r"(a[2]), "r"(a[3]), "r"(b0), "r"(b1));
}

// ================= pos = rel_h + rel_w (split) =================
__global__ void pos_kernel(const float *__restrict__ rel_h,
                           const float *__restrict__ rel_w) {
    int idx = blockIdx.x * 256 + threadIdx.x;   // (h*1024+n)*64+d
    int d  = idx & 63;
    int n  = (idx >> 6) & 1023;
    int hh = idx >> 16;
    int w  = n >> 5;
    int hw = n & 31;
    float v = rel_h[(hh * DH + d) * 32 + hw] + rel_w[(hh * DH + d) * 32 + w];
    __nv_bfloat16 bh_, bl_;
    bsplit(v, bh_, bl_);
    g_ph[idx] = bh_;
    g_pl[idx] = bl_;
}

// ================= projection GEMMs (FFMA2 mainloop, split epilogue) ========
__global__ __launch_bounds__(256, 2) void proj_kernel(
    const float *__restrict__ x,  const float *__restrict__ dsrc,
    const float *__restrict__ Wq, const float *__restrict__ bq,
    const float *__restrict__ Wk, const float *__restrict__ bk,
    const float *__restrict__ Wv, const float *__restrict__ bv) {
    const int p = blockIdx.z;
    const int b = blockIdx.y;
    const float *src  = (p == 0) ? x  : dsrc;
    const float *W    = (p == 0) ? Wq : (p == 1 ? Wk : Wv);
    const float *bias = (p == 0) ? bq : (p == 1 ? bk : bv);

    const int m0 = (blockIdx.x >> 2) * 128;
    const int o0 = (blockIdx.x & 3) * 128;

    __shared__ float As[16 * 130];
    __shared__ __align__(16) float Bs2[16 * 260];

    const int t  = threadIdx.x;
    const int tm = t & 15;
    const int to = t >> 4;

    u64 acc2[4][8];
    #pragma unroll
    for (int g = 0; g < 4; g++)
        #pragma unroll
        for (int j = 0; j < 8; j++) acc2[g][j] = 0ull;

    const float *srcb = src + (size_t)b * CC * NPIX;

    for (int kt = 0; kt < 32; kt++) {
        const int k0 = kt * 16;
        #pragma unroll
        for (int l2 = 0; l2 < 2; l2++) {
            int c = t + l2 * 256;
            int k = c >> 5, m4 = (c & 31) * 4;
            float4 xv = *(const float4 *)&srcb[(size_t)(k0 + k) * NPIX + m0 + m4];
            float *ar = &As[k * 130 + m4];
            *(float2 *)ar       = make_float2(xv.x, xv.y);
            *(float2 *)(ar + 2) = make_float2(xv.z, xv.w);
        }
        {
            int o = t >> 1, k8 = (t & 1) * 8;
            float4 w0 = *(const float4 *)&W[(size_t)(o0 + o) * CC + k0 + k8];
            float4 w1 = *(const float4 *)&W[(size_t)(o0 + o) * CC + k0 + k8 + 4];
            float vals[8] = {w0.x, w0.y, w0.z, w0.w, w1.x, w1.y, w1.z, w1.w};
            #pragma unroll
            for (int e = 0; e < 8; e++)
                *(float2 *)&Bs2[(k8 + e) * 260 + 2 * o] = make_float2(vals[e], vals[e]);
        }
        __syncthreads();
        #pragma unroll 4
        for (int k = 0; k < 16; k++) {
            u64 a2[4];
            #pragma unroll
            for (int g = 0; g < 4; g++)
                a2[g] = *(const u64 *)&As[k * 130 + 2 * tm + 32 * g];
            ulonglong2 bvv[4];
            #pragma unroll
            for (int jc = 0; jc < 4; jc++)
                bvv[jc] = *(const ulonglong2 *)&Bs2[k * 260 + 16 * to + 4 * jc];
            #pragma unroll
            for (int g = 0; g < 4; g++)
                #pragma unroll
                for (int jc = 0; jc < 4; jc++) {
                    ffma2(acc2[g][2 * jc],     a2[g], bvv[jc].x);
                    ffma2(acc2[g][2 * jc + 1], a2[g], bvv[jc].y);
                }
        }
        __syncthreads();
    }

    const int o_base = o0 + to * 8;
    float bia[8];
    #pragma unroll
    for (int j = 0; j < 8; j++) bia[j] = bias[o_base + j];
    const int head = o_base >> 6;
    const int d0   = o_base & 63;
    const int bh   = b * 8 + head;

    __nv_bfloat16 *dh = (p == 0) ? g_qh : (p == 1 ? g_kh : g_vh);
    __nv_bfloat16 *dl = (p == 0) ? g_ql : (p == 1 ? g_kl : g_vl);
    #pragma unroll
    for (int g = 0; g < 4; g++) {
        int mm = m0 + 2 * tm + 32 * g;
        float y0[8], y1[8];
        #pragma unroll
        for (int j = 0; j < 8; j++) {
            float l_, h_; unpack2(acc2[g][j], l_, h_);
            y0[j] = l_ + bia[j]; y1[j] = h_ + bia[j];
        }
        __align__(16) __nv_bfloat16 th[8], tl[8];
        #pragma unroll
        for (int j = 0; j < 8; j++) bsplit(y0[j], th[j], tl[j]);
        size_t base0 = ((size_t)bh * NPIX + mm) * DH + d0;
        *(uint4 *)&dh[base0] = *(const uint4 *)th;
        *(uint4 *)&dl[base0] = *(const uint4 *)tl;
        #pragma unroll
        for (int j = 0; j < 8; j++) bsplit(y1[j], th[j], tl[j]);
        size_t base1 = ((size_t)bh * NPIX + mm + 1) * DH + d0;
        *(uint4 *)&dh[base1] = *(const uint4 *)th;
        *(uint4 *)&dl[base1] = *(const uint4 *)tl;
    }
}

// ================= HMMA flash attention =================
// Block: (i-tile 128, bh). 8 warps; warp w owns rows 16w..16w+15.
// S = [Q|pos]·[K|Q]^T, 3-split bf16 HMMA, fp32 regs. Softmax warp-local.
// P -> smem bf16 hi/lo; PV accumulates into O regs via HMMA (ldmatrix.trans V).
#define SM_AH 0
#define SM_AL 34816
#define SM_BH 69632
#define SM_BL 87040
#define SM_VH 104448
#define SM_VL 113664
#define SM_PH 122880
#define SM_PL 141312
#define ATTN_SMEM 159744
// row strides in BYTES: A/B = 272 (136 bf16), V/P = 144 (72 bf16)

__global__ __launch_bounds__(256, 1) void attn_kernel(float *__restrict__ out) {
    extern __shared__ __align__(16) char smem[];
    const uint32_t sb = smem_to_u32(smem);

    const int tid  = threadIdx.x;
    const int w    = tid >> 5;
    const int lane = tid & 31;
    const int i0   = blockIdx.x * 128;
    const int bh   = blockIdx.y;
    const int hd   = bh & 7;

    // per-lane ldmatrix offsets (bytes)
    const uint32_t a_off = (lane & 15) * 272 + (lane >> 4) * 16;                    // A/B 16x16 non-trans
    const uint32_t b_off = ((lane >> 4) * 8 + (lane & 7)) * 272 + ((lane >> 3) & 1) * 16; // B n-pair
    const uint32_t v_off = (((lane >> 3) & 1) * 8 + (lane & 7)) * 144 + (lane >> 4) * 16; // V trans
    const uint32_t p_off = (lane & 15) * 144 + (lane >> 4) * 16;                    // P 16x16

    // ---- stage A = [q_i | pos_i] hi/lo (once) ----
    for (int c = tid; c < 4096; c += 256) {
        int mat = c >> 11, cc = c & 2047;
        int i = cc >> 4, k8 = (cc & 15) * 8;
        const __nv_bfloat16 *s = (k8 < 64)
            ? (mat ? g_ql : g_qh) + ((size_t)bh * NPIX + i0 + i) * DH + k8
            : (mat ? g_pl : g_ph) + ((size_t)hd * NPIX + i0 + i) * DH + (k8 - 64);
        *(uint4 *)(smem + (mat ? SM_AL : SM_AH) + i * 272 + k8 * 2) = *(const uint4 *)s;
    }

    float m0v = -1e30f, m1v = -1e30f, l0v = 0.f, l1v = 0.f;
    float O[8][4];
    #pragma unroll
    for (int c = 0; c < 8; c++)
        #pragma unroll
        for (int e = 0; e < 4; e++) O[c][e] = 0.f;

    for (int kt = 0; kt < 16; kt++) {
        const int j0 = kt * 64;
        // ---- stage B = [k_j | q_j] hi/lo and V hi/lo ----
        for (int c = tid; c < 2048; c += 256) {
            int mat = c >> 10, cc = c & 1023;
            int j = cc >> 4, k8 = (cc & 15) * 8;
            const __nv_bfloat16 *s = (k8 < 64)
                ? (mat ? g_kl : g_kh) + ((size_t)bh * NPIX + j0 + j) * DH + k8
                : (mat ? g_ql : g_qh) + ((size_t)bh * NPIX + j0 + j) * DH + (k8 - 64);
            *(uint4 *)(smem + (mat ? SM_BL : SM_BH) + j * 272 + k8 * 2) = *(const uint4 *)s;
        }
        for (int c = tid; c < 1024; c += 256) {
            int mat = c >> 9, cc = c & 511;
            int j = cc >> 3, d8 = (cc & 7) * 8;
            const __nv_bfloat16 *s =
                (mat ? g_vl : g_vh) + ((size_t)bh * NPIX + j0 + j) * DH + d8;
            *(uint4 *)(smem + (mat ? SM_VL : SM_VH) + j * 144 + d8 * 2) = *(const uint4 *)s;
        }
        __syncthreads();

        // ---- S = A·B^T  (16x64 per warp, k=128, 3 splits) ----
        float s[8][4];
        #pragma unroll
        for (int c = 0; c < 8; c++)
            #pragma unroll
            for (int e = 0; e < 4; e++) s[c][e] = 0.f;
        #pragma unroll
        for (int ks = 0; ks < 8; ks++) {
            uint32_t aH[4], aL[4];
            uint32_t abase = w * 16 * 272 + ks * 32 + a_off;
            ldsm4(aH, sb + SM_AH + abase);
            ldsm4(aL, sb + SM_AL + abase);
            #pragma unroll
            for (int np = 0; np < 4; np++) {
                uint32_t bH[4], bL[4];
                uint32_t bbase = np * 16 * 272 + ks * 32 + b_off;
                ldsm4(bH, sb + SM_BH + bbase);
                ldsm4(bL, sb + SM_BL + bbase);
                hmma(s[2 * np],     aH, bH[0], bH[1]);
                hmma(s[2 * np + 1], aH, bH[2], bH[3]);
                hmma(s[2 * np],     aH, bL[0], bL[1]);
                hmma(s[2 * np + 1], aH, bL[2], bL[3]);
                hmma(s[2 * np],     aL, bH[0], bH[1]);
                hmma(s[2 * np + 1], aL, bH[2], bH[3]);
            }
        }

        // ---- warp-local online softmax (row r = lane/4 and r+8) ----
        float pm0 = s[0][0], pm1 = s[0][2];
        #pragma unroll
        for (int c = 0; c < 8; c++) {
            pm0 = fmaxf(pm0, fmaxf(s[c][0], s[c][1]));
            pm1 = fmaxf(pm1, fmaxf(s[c][2], s[c][3]));
        }
        pm0 = fmaxf(pm0, __shfl_xor_sync(0xffffffffu, pm0, 1));
        pm0 = fmaxf(pm0, __shfl_xor_sync(0xffffffffu, pm0, 2));
        pm1 = fmaxf(pm1, __shfl_xor_sync(0xffffffffu, pm1, 1));
        pm1 = fmaxf(pm1, __shfl_xor_sync(0xffffffffu, pm1, 2));
        float mn0 = fmaxf(m0v, pm0), mn1 = fmaxf(m1v, pm1);
        float sc0 = __expf(m0v - mn0), sc1 = __expf(m1v - mn1);
        m0v = mn0; m1v = mn1;
        float sum0 = 0.f, sum1 = 0.f;
        const int prow0 = w * 16 + (lane >> 2);
        const uint32_t pcol = (lane & 3) * 2;
        #pragma unroll
        for (int c = 0; c < 8; c++) {
            float p0 = __expf(s[c][0] - mn0);
            float p1 = __expf(s[c][1] - mn0);
            float p2 = __expf(s[c][2] - mn1);
            float p3 = __expf(s[c][3] - mn1);
            sum0 += p0 + p1; sum1 += p2 + p3;
            // split and store P
            __nv_bfloat16 h0 = __float2bfloat16(p0), h1 = __float2bfloat16(p1);
            __nv_bfloat16 h2 = __float2bfloat16(p2), h3 = __float2bfloat16(p3);
            __nv_bfloat162 hv01; hv01.x = h0; hv01.y = h1;
            __nv_bfloat162 hv23; hv23.x = h2; hv23.y = h3;
            __nv_bfloat162 lv01, lv23;
            lv01.x = __float2bfloat16(p0 - __bfloat162float(h0));
            lv01.y = __float2bfloat16(p1 - __bfloat162float(h1));
            lv23.x = __float2bfloat16(p2 - __bfloat162float(h2));
            lv23.y = __float2bfloat16(p3 - __bfloat162float(h3));
            uint32_t off0 = prow0 * 144 + (8 * c + pcol) * 2;
            uint32_t off1 = off0 + 8 * 144;
            *(__nv_bfloat162 *)(smem + SM_PH + off0) = hv01;
            *(__nv_bfloat162 *)(smem + SM_PH + off1) = hv23;
            *(__nv_bfloat162 *)(smem + SM_PL + off0) = lv01;
            *(__nv_bfloat162 *)(smem + SM_PL + off1) = lv23;
        }
        sum0 += __shfl_xor_sync(0xffffffffu, sum0, 1);
        sum0 += __shfl_xor_sync(0xffffffffu, sum0, 2);
        sum1 += __shfl_xor_sync(0xffffffffu, sum1, 1);
        sum1 += __shfl_xor_sync(0xffffffffu, sum1, 2);
        l0v = l0v * sc0 + sum0;
        l1v = l1v * sc1 + sum1;
        // rescale O
        #pragma unroll
        for (int c = 0; c < 8; c++) {
            O[c][0] *= sc0; O[c][1] *= sc0;
            O[c][2] *= sc1; O[c][3] *= sc1;
        }
        __syncthreads();   // P visible to all (ldmatrix reads own rows only, but keep safe)

        // ---- O += P·V (k=64 over j, 3 splits, ldmatrix.trans for V) ----
        #pragma unroll
        for (int ks = 0; ks < 4; ks++) {
            uint32_t aH[4], aL[4];
            uint32_t pbase = w * 16 * 144 + ks * 32 + p_off;
            ldsm4(aH, sb + SM_PH + pbase);
            ldsm4(aL, sb + SM_PL + pbase);
            #pragma unroll
            for (int dp = 0; dp < 4; dp++) {
                uint32_t bH[4], bL[4];
                uint32_t vbase = ks * 16 * 144 + dp * 32 + v_off;
                ldsm4t(bH, sb + SM_VH + vbase);
                ldsm4t(bL, sb + SM_VL + vbase);
                hmma(O[2 * dp],     aH, bH[0], bH[1]);
                hmma(O[2 * dp + 1], aH, bH[2], bH[3]);
                hmma(O[2 * dp],     aH, bL[0], bL[1]);
                hmma(O[2 * dp + 1], aH, bL[2], bL[3]);
                hmma(O[2 * dp],     aL, bH[0], bH[1]);
                hmma(O[2 * dp + 1], aL, bH[2], bH[3]);
            }
        }
        __syncthreads();   // PV done reading B/V/P before next restage
    }

    // ---- epilogue: normalize, transpose via smem (reuse A region), store ----
    float rl0 = 1.0f / l0v, rl1 = 1.0f / l1v;
    float *ot = (float *)(smem + SM_AH);   // [64 d][136]
    {
        const int r0 = w * 16 + (lane >> 2);
        const int cq = (lane & 3) * 2;
        #pragma unroll
        for (int c = 0; c < 8; c++) {
            int d0 = 8 * c + cq;
            ot[d0 * 136 + r0]           = O[c][0] * rl0;
            ot[(d0 + 1) * 136 + r0]     = O[c][1] * rl0;
            ot[d0 * 136 + r0 + 8]       = O[c][2] * rl1;
            ot[(d0 + 1) * 136 + r0 + 8] = O[c][3] * rl1;
        }
    }
    __syncthreads();
    {
        int dr = tid >> 2, ch = (tid & 3) * 32;
        const float *src = ot + dr * 136 + ch;
        float *ob = out + (((size_t)(bh >> 3) * 512) + hd * 64 + dr) * NPIX + i0 + ch;
        #pragma unroll
        for (int e = 0; e < 8; e++)
            *(float4 *)(ob + 4 * e) = *(const float4 *)(src + 4 * e);
    }
}

// ================= launch =================
extern "C" void kernel_launch(void *const *d_in, const int *in_sizes, int n_in,
                              void *d_out, int out_size) {
    const float *x     = (const float *)d_in[0];
    const float *d     = (const float *)d_in[1];
    const float *Wq    = (const float *)d_in[2];
    const float *bq    = (const float *)d_in[3];
    const float *Wk    = (const float *)d_in[4];
    const float *bk    = (const float *)d_in[5];
    const float *Wv    = (const float *)d_in[6];
    const float *bv    = (const float *)d_in[7];
    const float *rel_h = (const float *)d_in[8];
    const float *rel_w = (const float *)d_in[9];
    float *out = (float *)d_out;

    cudaFuncSetAttribute(attn_kernel,
                         cudaFuncAttributeMaxDynamicSharedMemorySize, ATTN_SMEM);

    pos_kernel<<<HEADS * NPIX * DH / 256, 256>>>(rel_h, rel_w);
    proj_kernel<<<dim3(32, NB, 3), 256>>>(x, d, Wq, bq, Wk, bk, Wv, bv);
    attn_kernel<<<dim3(8, NBH), 256, ATTN_SMEM>>>(out);
}

// round 7
// speedup vs baseline: 1.8270x; 1.8270x over previous
#include <cuda_runtime.h>
#include <cuda_bf16.h>
#include <cstdint>

#define HEADS 8
#define DH    64
#define NPIX  1024
#define CC    512
#define NB    8
#define NBH   64

typedef unsigned long long u64;

// ---- scratch: bf16 hi/lo split operands (allocation-guard-safe globals) ----
__device__ __align__(16) __nv_bfloat16 g_qh[NBH * NPIX * DH];  // [bh][n][d]
__device__ __align__(16) __nv_bfloat16 g_ql[NBH * NPIX * DH];
__device__ __align__(16) __nv_bfloat16 g_kh[NBH * NPIX * DH];
__device__ __align__(16) __nv_bfloat16 g_kl[NBH * NPIX * DH];
__device__ __align__(16) __nv_bfloat16 g_vh[NBH * NPIX * DH];  // [bh][n][d]
__device__ __align__(16) __nv_bfloat16 g_vl[NBH * NPIX * DH];
__device__ __align__(16) __nv_bfloat16 g_ph[HEADS * NPIX * DH]; // [h][n][d]
__device__ __align__(16) __nv_bfloat16 g_pl[HEADS * NPIX * DH];

// ---- packed f32x2 helpers (projection mainloop) ----
__device__ __forceinline__ void ffma2(u64 &c, u64 a, u64 b) {
    asm("fma.rn.f32x2 %0, %1, %2, %0;" : "+l"(c) : "l"(a), "l"(b));
}
__device__ __forceinline__ void unpack2(u64 v, float &x, float &y) {
    asm("mov.b64 {%0, %1}, %2;" : "=f"(x), "=f"(y) : "l"(v));
}
__device__ __forceinline__ void bsplit(float y, __nv_bfloat16 &hi, __nv_bfloat16 &lo) {
    hi = __float2bfloat16(y);
    lo = __float2bfloat16(y - __bfloat162float(hi));
}

// ---- mma.sync / ldmatrix / cp.async primitives (baseline PTX, sm_80+) ----
__device__ __forceinline__ uint32_t smem_to_u32(const void *p) {
    uint32_t a;
    asm("{ .reg .u64 t; cvta.to.shared.u64 t, %1; cvt.u32.u64 %0, t; }"
        : "=r"(a) : "l"(p));
    return a;
}
__device__ __forceinline__ void ldsm4(uint32_t *r, uint32_t addr) {
    asm volatile("ldmatrix.sync.aligned.m8n8.x4.shared.b16 {%0,%1,%2,%3}, [%4];"
                 : "=r"(r[0]), "=r"(r[1]), "=r"(r[2]), "=r"(r[3]) : "r"(addr));
}
__device__ __forceinline__ void ldsm4t(uint32_t *r, uint32_t addr) {
    asm volatile("ldmatrix.sync.aligned.m8n8.x4.trans.shared.b16 {%0,%1,%2,%3}, [%4];"
                 : "=r"(r[0]), "=r"(r[1]), "=r"(r[2]), "=r"(r[3]) : "r"(addr));
}
__device__ __forceinline__ void hmma(float *c, const uint32_t *a, uint32_t b0, uint32_t b1) {
    asm volatile(
        "mma.sync.aligned.m16n8k16.row.col.f32.bf16.bf16.f32 "
        "{%0,%1,%2,%3}, {%4,%5,%6,%7}, {%8,%9}, {%0,%1,%2,%3};"
        : "+f"(c[0]), "+f"(c[1]), "+f"(c[2]), "+f"(c[3])
        : "r"(a[0]), "r"(a[1]), "r"(a[2]), "r"(a[3]), "r"(b0), "r"(b1));
}
__device__ __forceinline__ void cp16(uint32_t s, const void *g) {
    asm volatile("cp.async.cg.shared.global [%0], [%1], 16;" :: "r"(s), "l"(g));
}
#define CP_COMMIT() asm volatile("cp.async.commit_group;" ::: "memory")
#define CP_WAIT0()  asm volatile("cp.async.wait_group 0;" ::: "memory")

// pack (e -> low half, o -> high half) as bf16x2
__device__ __forceinline__ uint32_t packbf(float e, float o) {
    uint32_t r;
    asm("cvt.rn.bf16x2.f32 %0, %1, %2;" : "=r"(r) : "f"(o), "f"(e));
    return r;
}
__device__ __forceinline__ float lo_of(uint32_t r) { return __uint_as_float(r << 16); }
__device__ __forceinline__ float hi_of(uint32_t r) { return __uint_as_float(r & 0xFFFF0000u); }

// ================= pos = rel_h + rel_w (split) =================
__global__ void pos_kernel(const float *__restrict__ rel_h,
                           const float *__restrict__ rel_w) {
    int idx = blockIdx.x * 256 + threadIdx.x;   // (h*1024+n)*64+d
    int d  = idx & 63;
    int n  = (idx >> 6) & 1023;
    int hh = idx >> 16;
    int w  = n >> 5;
    int hw = n & 31;
    float v = rel_h[(hh * DH + d) * 32 + hw] + rel_w[(hh * DH + d) * 32 + w];
    __nv_bfloat16 bh_, bl_;
    bsplit(v, bh_, bl_);
    g_ph[idx] = bh_;
    g_pl[idx] = bl_;
}

// ================= projection GEMMs (FFMA2 mainloop, split epilogue) ========
__global__ __launch_bounds__(256, 2) void proj_kernel(
    const float *__restrict__ x,  const float *__restrict__ dsrc,
    const float *__restrict__ Wq, const float *__restrict__ bq,
    const float *__restrict__ Wk, const float *__restrict__ bk,
    const float *__restrict__ Wv, const float *__restrict__ bv) {
    const int p = blockIdx.z;
    const int b = blockIdx.y;
    const float *src  = (p == 0) ? x  : dsrc;
    const float *W    = (p == 0) ? Wq : (p == 1 ? Wk : Wv);
    const float *bias = (p == 0) ? bq : (p == 1 ? bk : bv);

    const int m0 = (blockIdx.x >> 2) * 128;
    const int o0 = (blockIdx.x & 3) * 128;

    __shared__ float As[16 * 130];
    __shared__ __align__(16) float Bs2[16 * 260];

    const int t  = threadIdx.x;
    const int tm = t & 15;
    const int to = t >> 4;

    u64 acc2[4][8];
    #pragma unroll
    for (int g = 0; g < 4; g++)
        #pragma unroll
        for (int j = 0; j < 8; j++) acc2[g][j] = 0ull;

    const float *srcb = src + (size_t)b * CC * NPIX;

    for (int kt = 0; kt < 32; kt++) {
        const int k0 = kt * 16;
        #pragma unroll
        for (int l2 = 0; l2 < 2; l2++) {
            int c = t + l2 * 256;
            int k = c >> 5, m4 = (c & 31) * 4;
            float4 xv = *(const float4 *)&srcb[(size_t)(k0 + k) * NPIX + m0 + m4];
            float *ar = &As[k * 130 + m4];
            *(float2 *)ar       = make_float2(xv.x, xv.y);
            *(float2 *)(ar + 2) = make_float2(xv.z, xv.w);
        }
        {
            int o = t >> 1, k8 = (t & 1) * 8;
            float4 w0 = *(const float4 *)&W[(size_t)(o0 + o) * CC + k0 + k8];
            float4 w1 = *(const float4 *)&W[(size_t)(o0 + o) * CC + k0 + k8 + 4];
            float vals[8] = {w0.x, w0.y, w0.z, w0.w, w1.x, w1.y, w1.z, w1.w};
            #pragma unroll
            for (int e = 0; e < 8; e++)
                *(float2 *)&Bs2[(k8 + e) * 260 + 2 * o] = make_float2(vals[e], vals[e]);
        }
        __syncthreads();
        #pragma unroll 4
        for (int k = 0; k < 16; k++) {
            u64 a2[4];
            #pragma unroll
            for (int g = 0; g < 4; g++)
                a2[g] = *(const u64 *)&As[k * 130 + 2 * tm + 32 * g];
            ulonglong2 bvv[4];
            #pragma unroll
            for (int jc = 0; jc < 4; jc++)
                bvv[jc] = *(const ulonglong2 *)&Bs2[k * 260 + 16 * to + 4 * jc];
            #pragma unroll
            for (int g = 0; g < 4; g++)
                #pragma unroll
                for (int jc = 0; jc < 4; jc++) {
                    ffma2(acc2[g][2 * jc],     a2[g], bvv[jc].x);
                    ffma2(acc2[g][2 * jc + 1], a2[g], bvv[jc].y);
                }
        }
        __syncthreads();
    }

    const int o_base = o0 + to * 8;
    float bia[8];
    #pragma unroll
    for (int j = 0; j < 8; j++) bia[j] = bias[o_base + j];
    const int head = o_base >> 6;
    const int d0   = o_base & 63;
    const int bh   = b * 8 + head;

    __nv_bfloat16 *dh = (p == 0) ? g_qh : (p == 1 ? g_kh : g_vh);
    __nv_bfloat16 *dl = (p == 0) ? g_ql : (p == 1 ? g_kl : g_vl);
    #pragma unroll
    for (int g = 0; g < 4; g++) {
        int mm = m0 + 2 * tm + 32 * g;
        float y0[8], y1[8];
        #pragma unroll
        for (int j = 0; j < 8; j++) {
            float l_, h_; unpack2(acc2[g][j], l_, h_);
            y0[j] = l_ + bia[j]; y1[j] = h_ + bia[j];
        }
        __align__(16) __nv_bfloat16 th[8], tl[8];
        #pragma unroll
        for (int j = 0; j < 8; j++) bsplit(y0[j], th[j], tl[j]);
        size_t base0 = ((size_t)bh * NPIX + mm) * DH + d0;
        *(uint4 *)&dh[base0] = *(const uint4 *)th;
        *(uint4 *)&dl[base0] = *(const uint4 *)tl;
        #pragma unroll
        for (int j = 0; j < 8; j++) bsplit(y1[j], th[j], tl[j]);
        size_t base1 = ((size_t)bh * NPIX + mm + 1) * DH + d0;
        *(uint4 *)&dh[base1] = *(const uint4 *)th;
        *(uint4 *)&dl[base1] = *(const uint4 *)tl;
    }
}

// ================= HMMA flash attention v2 =================
// 512 threads = 16 warps: wm = w&7 (16-row strip), wn = w>>3 (32-col half).
// Each warp: independent flash over its j-half; merge at epilogue.
// P kept in registers (acc layout == A-frag layout). cp.async double buffer.
#define SM_AH   0
#define SM_AL   34816
#define BUF0    69632
#define BUF1    122880
#define OB_BH   0
#define OB_BL   17408
#define OB_VH   34816
#define OB_VL   44032
#define SC_OACC 4096
#define SC_OT   40960
#define ATTN_SMEM 176128
// strides (bytes): A/B rows 272, V rows 144, OACC 68 f32, OT 136 f32

__device__ __forceinline__ void stage_bv(uint32_t bufsb, int bh, int j0, int tid) {
    #pragma unroll
    for (int l = 0; l < 4; l++) {
        int c = tid + l * 512;              // 0..2047: B hi/lo
        int mat = c >> 10, cc = c & 1023;
        int j = cc >> 4, k8 = (cc & 15) * 8;
        const __nv_bfloat16 *s = (k8 < 64)
            ? (mat ? g_kl : g_kh) + ((size_t)bh * NPIX + j0 + j) * DH + k8
            : (mat ? g_ql : g_qh) + ((size_t)bh * NPIX + j0 + j) * DH + (k8 - 64);
        cp16(bufsb + (mat ? OB_BL : OB_BH) + j * 272 + k8 * 2, s);
    }
    #pragma unroll
    for (int l = 0; l < 2; l++) {
        int c = tid + l * 512;              // 0..1023: V hi/lo
        int mat = c >> 9, cc = c & 511;
        int j = cc >> 3, d8 = (cc & 7) * 8;
        const __nv_bfloat16 *s =
            (mat ? g_vl : g_vh) + ((size_t)bh * NPIX + j0 + j) * DH + d8;
        cp16(bufsb + (mat ? OB_VL : OB_VH) + j * 144 + d8 * 2, s);
    }
}

__global__ __launch_bounds__(512, 1) void attn_kernel(float *__restrict__ out) {
    extern __shared__ __align__(16) char smem[];
    const uint32_t sb = smem_to_u32(smem);

    const int tid  = threadIdx.x;
    const int w    = tid >> 5;
    const int lane = tid & 31;
    const int wm   = w & 7;
    const int wn   = w >> 3;
    const int i0   = blockIdx.x * 128;
    const int bh   = blockIdx.y;
    const int hd   = bh & 7;

    // per-lane ldmatrix offsets (bytes)
    const uint32_t a_off = (lane & 15) * 272 + (lane >> 4) * 16;
    const uint32_t b_off = ((lane >> 4) * 8 + (lane & 7)) * 272 + ((lane >> 3) & 1) * 16;
    const uint32_t v_off = (((lane >> 3) & 1) * 8 + (lane & 7)) * 144 + (lane >> 4) * 16;

    // prefetch B/V(kt=0)
    stage_bv(sb + BUF0, bh, 0, tid);
    CP_COMMIT();

    // stage A = [q_i | pos_i] hi/lo (plain loads, once)
    for (int c = tid; c < 4096; c += 512) {
        int mat = c >> 11, cc = c & 2047;
        int i = cc >> 4, k8 = (cc & 15) * 8;
        const __nv_bfloat16 *s = (k8 < 64)
            ? (mat ? g_ql : g_qh) + ((size_t)bh * NPIX + i0 + i) * DH + k8
            : (mat ? g_pl : g_ph) + ((size_t)hd * NPIX + i0 + i) * DH + (k8 - 64);
        *(uint4 *)(smem + (mat ? SM_AL : SM_AH) + i * 272 + k8 * 2) = *(const uint4 *)s;
    }

    float mv[2] = {-1e30f, -1e30f}, lv[2] = {0.f, 0.f};
    float O[8][4];
    #pragma unroll
    for (int c = 0; c < 8; c++)
        #pragma unroll
        for (int e = 0; e < 4; e++) O[c][e] = 0.f;

    for (int kt = 0; kt < 16; kt++) {
        const uint32_t buf = sb + ((kt & 1) ? BUF1 : BUF0);
        CP_WAIT0();
        __syncthreads();
        if (kt < 15) {
            stage_bv(sb + (((kt + 1) & 1) ? BUF1 : BUF0), bh, (kt + 1) * 64, tid);
            CP_COMMIT();
        }

        // ---- S = A·B^T (16 rows x 32 cols per warp, k=128, 3 splits) ----
        float s[4][4];
        #pragma unroll
        for (int np = 0; np < 4; np++)
            #pragma unroll
            for (int e = 0; e < 4; e++) s[np][e] = 0.f;
        #pragma unroll
        for (int ks = 0; ks < 8; ks++) {
            uint32_t aH[4], aL[4];
            uint32_t abase = wm * 16 * 272 + ks * 32 + a_off;
            ldsm4(aH, sb + SM_AH + abase);
            ldsm4(aL, sb + SM_AL + abase);
            #pragma unroll
            for (int nt = 0; nt < 2; nt++) {
                uint32_t bH[4], bL[4];
                uint32_t bbase = (wn * 32 + nt * 16) * 272 + ks * 32 + b_off;
                ldsm4(bH, buf + OB_BH + bbase);
                ldsm4(bL, buf + OB_BL + bbase);
                hmma(s[2 * nt],     aH, bH[0], bH[1]);
                hmma(s[2 * nt + 1], aH, bH[2], bH[3]);
                hmma(s[2 * nt],     aH, bL[0], bL[1]);
                hmma(s[2 * nt + 1], aH, bL[2], bL[3]);
                hmma(s[2 * nt],     aL, bH[0], bH[1]);
                hmma(s[2 * nt + 1], aL, bH[2], bH[3]);
            }
        }

        // ---- warp-local online softmax over own 32 cols ----
        float pm0 = s[0][0], pm1 = s[0][2];
        #pragma unroll
        for (int np = 0; np < 4; np++) {
            pm0 = fmaxf(pm0, fmaxf(s[np][0], s[np][1]));
            pm1 = fmaxf(pm1, fmaxf(s[np][2], s[np][3]));
        }
        pm0 = fmaxf(pm0, __shfl_xor_sync(0xffffffffu, pm0, 1));
        pm0 = fmaxf(pm0, __shfl_xor_sync(0xffffffffu, pm0, 2));
        pm1 = fmaxf(pm1, __shfl_xor_sync(0xffffffffu, pm1, 1));
        pm1 = fmaxf(pm1, __shfl_xor_sync(0xffffffffu, pm1, 2));
        float mn0 = fmaxf(mv[0], pm0), mn1 = fmaxf(mv[1], pm1);
        float sc0 = __expf(mv[0] - mn0), sc1 = __expf(mv[1] - mn1);
        mv[0] = mn0; mv[1] = mn1;
        float sum0 = 0.f, sum1 = 0.f;
        #pragma unroll
        for (int np = 0; np < 4; np++) {
            s[np][0] = __expf(s[np][0] - mn0);
            s[np][1] = __expf(s[np][1] - mn0);
            s[np][2] = __expf(s[np][2] - mn1);
            s[np][3] = __expf(s[np][3] - mn1);
            sum0 += s[np][0] + s[np][1];
            sum1 += s[np][2] + s[np][3];
        }
        sum0 += __shfl_xor_sync(0xffffffffu, sum0, 1);
        sum0 += __shfl_xor_sync(0xffffffffu, sum0, 2);
        sum1 += __shfl_xor_sync(0xffffffffu, sum1, 1);
        sum1 += __shfl_xor_sync(0xffffffffu, sum1, 2);
        lv[0] = lv[0] * sc0 + sum0;
        lv[1] = lv[1] * sc1 + sum1;
        #pragma unroll
        for (int c = 0; c < 8; c++) {
            O[c][0] *= sc0; O[c][1] *= sc0;
            O[c][2] *= sc1; O[c][3] *= sc1;
        }

        // ---- P fragments directly from acc regs (hi/lo split) ----
        uint32_t pH[2][4], pL[2][4];
        #pragma unroll
        for (int kk = 0; kk < 2; kk++) {
            #pragma unroll
            for (int hh = 0; hh < 2; hh++) {       // acc tile 2kk+hh
                float e0 = s[2 * kk + hh][0], o0 = s[2 * kk + hh][1];
                float e1 = s[2 * kk + hh][2], o1 = s[2 * kk + hh][3];
                uint32_t h0 = packbf(e0, o0);
                uint32_t h1 = packbf(e1, o1);
                pH[kk][2 * hh]     = h0;
                pH[kk][2 * hh + 1] = h1;
                pL[kk][2 * hh]     = packbf(e0 - lo_of(h0), o0 - hi_of(h0));
                pL[kk][2 * hh + 1] = packbf(e1 - lo_of(h1), o1 - hi_of(h1));
            }
        }

        // ---- O += P·V over own j-half (k=32, 3 splits) ----
        #pragma unroll
        for (int kk = 0; kk < 2; kk++) {
            uint32_t vrow = (wn * 32 + kk * 16) * 144;
            #pragma unroll
            for (int dp = 0; dp < 4; dp++) {
                uint32_t vH[4], vL[4];
                uint32_t vbase = vrow + dp * 32 + v_off;
                ldsm4t(vH, buf + OB_VH + vbase);
                ldsm4t(vL, buf + OB_VL + vbase);
                hmma(O[2 * dp],     pH[kk], vH[0], vH[1]);
                hmma(O[2 * dp + 1], pH[kk], vH[2], vH[3]);
                hmma(O[2 * dp],     pH[kk], vL[0], vL[1]);
                hmma(O[2 * dp + 1], pH[kk], vL[2], vL[3]);
                hmma(O[2 * dp],     pL[kk], vH[0], vH[1]);
                hmma(O[2 * dp + 1], pL[kk], vH[2], vH[3]);
            }
        }
    }

    // ---- epilogue: merge the two column-halves, normalize, store ----
    __syncthreads();                       // everyone done with A/B/V reads
    float *sm_m = (float *)smem;           // [2][128]
    float *sm_l = (float *)(smem + 1024);  // [2][128]
    const int r0 = wm * 16 + (lane >> 2);
    sm_m[wn * 128 + r0]     = mv[0];
    sm_m[wn * 128 + r0 + 8] = mv[1];
    sm_l[wn * 128 + r0]     = lv[0];
    sm_l[wn * 128 + r0 + 8] = lv[1];
    __syncthreads();
    float fs[2], lt[2];
    #pragma unroll
    for (int hh = 0; hh < 2; hh++) {
        int rr = r0 + 8 * hh;
        float mo = sm_m[(1 ^ wn) * 128 + rr];
        float lo2 = sm_l[(1 ^ wn) * 128 + rr];
        float mt = fmaxf(mv[hh], mo);
        fs[hh] = __expf(mv[hh] - mt);
        float fo = __expf(mo - mt);
        lt[hh] = lv[hh] * fs[hh] + lo2 * fo;
    }
    float *oacc = (float *)(smem + SC_OACC);   // [128][68]
    const int cq = 2 * (lane & 3);
    __syncthreads();
    if (wn == 1) {
        #pragma unroll
        for (int c = 0; c < 8; c++)
            #pragma unroll
            for (int hh = 0; hh < 2; hh++) {
                int rr = r0 + 8 * hh;
                oacc[rr * 68 + 8 * c + cq]     = O[c][2 * hh]     * fs[hh];
                oacc[rr * 68 + 8 * c + cq + 1] = O[c][2 * hh + 1] * fs[hh];
            }
    }
    __syncthreads();
    float *ot = (float *)(smem + SC_OT);       // [64 d][136]
    if (wn == 0) {
        #pragma unroll
        for (int c = 0; c < 8; c++)
            #pragma unroll
            for (int hh = 0; hh < 2; hh++) {
                int rr = r0 + 8 * hh;
                float rlt = 1.0f / lt[hh];
                int d0 = 8 * c + cq;
                ot[d0 * 136 + rr] =
                    (O[c][2 * hh] * fs[hh] + oacc[rr * 68 + d0]) * rlt;
                ot[(d0 + 1) * 136 + rr] =
                    (O[c][2 * hh + 1] * fs[hh] + oacc[rr * 68 + d0 + 1]) * rlt;
            }
    }
    __syncthreads();
    {
        int dr = tid >> 3, ch = (tid & 7) * 16;
        const float *src = ot + dr * 136 + ch;
        float *ob = out + (((size_t)(bh >> 3) * 512) + hd * 64 + dr) * NPIX + i0 + ch;
        #pragma unroll
        for (int e = 0; e < 4; e++)
            *(float4 *)(ob + 4 * e) = *(const float4 *)(src + 4 * e);
    }
}

// ================= launch =================
extern "C" void kernel_launch(void *const *d_in, const int *in_sizes, int n_in,
                              void *d_out, int out_size) {
    const float *x     = (const float *)d_in[0];
    const float *d     = (const float *)d_in[1];
    const float *Wq    = (const float *)d_in[2];
    const float *bq    = (const float *)d_in[3];
    const float *Wk    = (const float *)d_in[4];
    const float *bk    = (const float *)d_in[5];
    const float *Wv    = (const float *)d_in[6];
    const float *bv    = (const float *)d_in[7];
    const float *rel_h = (const float *)d_in[8];
    const float *rel_w = (const float *)d_in[9];
    float *out = (float *)d_out;

    cudaFuncSetAttribute(attn_kernel,
                         cudaFuncAttributeMaxDynamicSharedMemorySize, ATTN_SMEM);

    pos_kernel<<<HEADS * NPIX * DH / 256, 256>>>(rel_h, rel_w);
    proj_kernel<<<dim3(32, NB, 3), 256>>>(x, d, Wq, bq, Wk, bk, Wv, bv);
    attn_kernel<<<dim3(8, NBH), 512, ATTN_SMEM>>>(out);
}

// round 8
// speedup vs baseline: 3.0371x; 1.6623x over previous
#include <cuda_runtime.h>
#include <cuda_bf16.h>
#include <cstdint>

#define HEADS 8
#define DH    64
#define NPIX  1024
#define CC    512
#define NB    8
#define NBH   64
#define XSZ   (NB * CC * NPIX)   // 4194304
#define WSZ   (CC * CC)          // 262144

typedef unsigned long long u64;

// ---- scratch: bf16 hi/lo split operands (allocation-guard-safe globals) ----
__device__ __align__(16) __nv_bfloat16 g_qh[NBH * NPIX * DH];  // [bh][n][d]
__device__ __align__(16) __nv_bfloat16 g_ql[NBH * NPIX * DH];
__device__ __align__(16) __nv_bfloat16 g_kh[NBH * NPIX * DH];
__device__ __align__(16) __nv_bfloat16 g_kl[NBH * NPIX * DH];
__device__ __align__(16) __nv_bfloat16 g_vh[NBH * NPIX * DH];  // [bh][n][d]
__device__ __align__(16) __nv_bfloat16 g_vl[NBH * NPIX * DH];
__device__ __align__(16) __nv_bfloat16 g_ph[HEADS * NPIX * DH]; // [h][n][d]
__device__ __align__(16) __nv_bfloat16 g_pl[HEADS * NPIX * DH];
// inputs split for HMMA projections
__device__ __align__(16) __nv_bfloat16 g_xh[XSZ];   // x  [b][c][n]
__device__ __align__(16) __nv_bfloat16 g_xl[XSZ];
__device__ __align__(16) __nv_bfloat16 g_eh[XSZ];   // d  [b][c][n]
__device__ __align__(16) __nv_bfloat16 g_el[XSZ];
__device__ __align__(16) __nv_bfloat16 g_wh[3 * WSZ]; // Wq|Wk|Wv [o][c]
__device__ __align__(16) __nv_bfloat16 g_wl[3 * WSZ];

__device__ __forceinline__ void bsplit(float y, __nv_bfloat16 &hi, __nv_bfloat16 &lo) {
    hi = __float2bfloat16(y);
    lo = __float2bfloat16(y - __bfloat162float(hi));
}

// ---- mma.sync / ldmatrix / cp.async primitives (baseline PTX, sm_80+) ----
__device__ __forceinline__ uint32_t smem_to_u32(const void *p) {
    uint32_t a;
    asm("{ .reg .u64 t; cvta.to.shared.u64 t, %1; cvt.u32.u64 %0, t; }"
        : "=r"(a) : "l"(p));
    return a;
}
__device__ __forceinline__ void ldsm4(uint32_t *r, uint32_t addr) {
    asm volatile("ldmatrix.sync.aligned.m8n8.x4.shared.b16 {%0,%1,%2,%3}, [%4];"
                 : "=r"(r[0]), "=r"(r[1]), "=r"(r[2]), "=r"(r[3]) : "r"(addr));
}
__device__ __forceinline__ void ldsm4t(uint32_t *r, uint32_t addr) {
    asm volatile("ldmatrix.sync.aligned.m8n8.x4.trans.shared.b16 {%0,%1,%2,%3}, [%4];"
                 : "=r"(r[0]), "=r"(r[1]), "=r"(r[2]), "=r"(r[3]) : "r"(addr));
}
__device__ __forceinline__ void hmma(float *c, const uint32_t *a, uint32_t b0, uint32_t b1) {
    asm volatile(
        "mma.sync.aligned.m16n8k16.row.col.f32.bf16.bf16.f32 "
        "{%0,%1,%2,%3}, {%4,%5,%6,%7}, {%8,%9}, {%0,%1,%2,%3};"
        : "+f"(c[0]), "+f"(c[1]), "+f"(c[2]), "+f"(c[3])
        : "r"(a[0]), "r"(a[1]), "r"(a[2]), "r"(a[3]), "r"(b0), "r"(b1));
}
__device__ __forceinline__ void cp16(uint32_t s, const void *g) {
    asm volatile("cp.async.cg.shared.global [%0], [%1], 16;" :: "r"(s), "l"(g));
}
#define CP_COMMIT() asm volatile("cp.async.commit_group;" ::: "memory")
#define CP_WAIT0()  asm volatile("cp.async.wait_group 0;" ::: "memory")

__device__ __forceinline__ uint32_t packbf(float e, float o) {
    uint32_t r;
    asm("cvt.rn.bf16x2.f32 %0, %1, %2;" : "=r"(r) : "f"(o), "f"(e));
    return r;
}
__device__ __forceinline__ float lo_of(uint32_t r) { return __uint_as_float(r << 16); }
__device__ __forceinline__ float hi_of(uint32_t r) { return __uint_as_float(r & 0xFFFF0000u); }

// ================= split inputs/weights to bf16 hi/lo =================
__global__ void split_kernel(const float *__restrict__ x, const float *__restrict__ dsrc,
                             const float *__restrict__ Wq, const float *__restrict__ Wk,
                             const float *__restrict__ Wv) {
    size_t i4 = ((size_t)blockIdx.x * 256 + threadIdx.x) * 4;
    const float *s;
    __nv_bfloat16 *oh, *ol;
    size_t off;
    if (i4 < (size_t)XSZ) {
        s = x; oh = g_xh; ol = g_xl; off = i4;
    } else if (i4 < 2 * (size_t)XSZ) {
        s = dsrc; oh = g_eh; ol = g_el; off = i4 - XSZ;
    } else {
        size_t wi = i4 - 2 * (size_t)XSZ;
        int p = (int)(wi / WSZ);
        off = wi - (size_t)p * WSZ;
        s = (p == 0) ? Wq : (p == 1 ? Wk : Wv);
        oh = g_wh + (size_t)p * WSZ;
        ol = g_wl + (size_t)p * WSZ;
    }
    float4 v = *(const float4 *)&s[off];
    __align__(8) __nv_bfloat16 h[4], l[4];
    bsplit(v.x, h[0], l[0]); bsplit(v.y, h[1], l[1]);
    bsplit(v.z, h[2], l[2]); bsplit(v.w, h[3], l[3]);
    *(u64 *)&oh[off] = *(const u64 *)h;
    *(u64 *)&ol[off] = *(const u64 *)l;
}

// ================= pos = rel_h + rel_w (split) =================
__global__ void pos_kernel(const float *__restrict__ rel_h,
                           const float *__restrict__ rel_w) {
    int idx = blockIdx.x * 256 + threadIdx.x;   // (h*1024+n)*64+d
    int d  = idx & 63;
    int n  = (idx >> 6) & 1023;
    int hh = idx >> 16;
    int w  = n >> 5;
    int hw = n & 31;
    float v = rel_h[(hh * DH + d) * 32 + hw] + rel_w[(hh * DH + d) * 32 + w];
    __nv_bfloat16 bh_, bl_;
    bsplit(v, bh_, bl_);
    g_ph[idx] = bh_;
    g_pl[idx] = bl_;
}

// ================= HMMA projection GEMMs =================
// Block: 128 pixels (m) x 128 out (o), K=512 in 16 chunks of 32 (cp.async dbl buf).
// 256 thr / 8 warps: wm = w&3 (32-m strip), wn = w>>2 (64-o half).
// A = x^T from k-major memory via ldmatrix.trans; B = W[o][k] non-trans.
#define PB_AH 0
#define PB_AL 8704
#define PB_WH 17408
#define PB_WL 27648
#define PB_SZ 37888
#define PROJ_SMEM (2 * PB_SZ)

__device__ __forceinline__ void stage_proj(uint32_t bufsb,
                                           const __nv_bfloat16 *ah, const __nv_bfloat16 *al,
                                           const __nv_bfloat16 *wh, const __nv_bfloat16 *wl,
                                           int m0, int o0, int k0, int tid) {
    #pragma unroll
    for (int l = 0; l < 2; l++) {          // A hi
        int c = tid + l * 256;             // 0..511
        int k = c >> 4, mc = (c & 15) * 8;
        cp16(bufsb + PB_AH + k * 272 + (c & 15) * 16,
             ah + (size_t)(k0 + k) * NPIX + m0 + mc);
    }
    #pragma unroll
    for (int l = 0; l < 2; l++) {          // A lo
        int c = tid + l * 256;
        int k = c >> 4, mc = (c & 15) * 8;
        cp16(bufsb + PB_AL + k * 272 + (c & 15) * 16,
             al + (size_t)(k0 + k) * NPIX + m0 + mc);
    }
    #pragma unroll
    for (int l = 0; l < 2; l++) {          // W hi
        int c = tid + l * 256;
        int o = c >> 2, kc = (c & 3) * 8;
        cp16(bufsb + PB_WH + o * 80 + (c & 3) * 16,
             wh + (size_t)(o0 + o) * CC + k0 + kc);
    }
    #pragma unroll
    for (int l = 0; l < 2; l++) {          // W lo
        int c = tid + l * 256;
        int o = c >> 2, kc = (c & 3) * 8;
        cp16(bufsb + PB_WL + o * 80 + (c & 3) * 16,
             wl + (size_t)(o0 + o) * CC + k0 + kc);
    }
}

__global__ __launch_bounds__(256, 2) void proj_kernel(
    const float *__restrict__ bq, const float *__restrict__ bk,
    const float *__restrict__ bv) {
    extern __shared__ __align__(16) char psmem[];
    const uint32_t sb = smem_to_u32(psmem);

    const int p  = blockIdx.z;
    const int b  = blockIdx.y;
    const int m0 = (blockIdx.x >> 2) * 128;
    const int o0 = (blockIdx.x & 3) * 128;

    const int tid  = threadIdx.x;
    const int w    = tid >> 5;
    const int lane = tid & 31;
    const int wm   = w & 3;
    const int wn   = w >> 2;

    const __nv_bfloat16 *ah = ((p == 0) ? g_xh : g_eh) + (size_t)b * CC * NPIX;
    const __nv_bfloat16 *al = ((p == 0) ? g_xl : g_el) + (size_t)b * CC * NPIX;
    const __nv_bfloat16 *wh = g_wh + (size_t)p * WSZ;
    const __nv_bfloat16 *wl = g_wl + (size_t)p * WSZ;
    const float *bias = (p == 0) ? bq : (p == 1 ? bk : bv);

    // per-lane fragment offsets (bytes)
    const uint32_t at_base = (((lane >> 4) * 8) + (lane & 7)) * 272 +
                             wm * 64 + ((lane >> 3) & 1) * 16;
    const uint32_t wb_base = (((lane >> 4) * 8) + (lane & 7)) * 80 +
                             ((lane >> 3) & 1) * 16;

    float s[2][8][4];
    #pragma unroll
    for (int mt = 0; mt < 2; mt++)
        #pragma unroll
        for (int j = 0; j < 8; j++)
            #pragma unroll
            for (int e = 0; e < 4; e++) s[mt][j][e] = 0.f;

    stage_proj(sb, ah, al, wh, wl, m0, o0, 0, tid);
    CP_COMMIT();

    for (int kc = 0; kc < 16; kc++) {
        const uint32_t buf = sb + (kc & 1) * PB_SZ;
        CP_WAIT0();
        __syncthreads();
        if (kc < 15) {
            stage_proj(sb + ((kc + 1) & 1) * PB_SZ, ah, al, wh, wl,
                       m0, o0, (kc + 1) * 32, tid);
            CP_COMMIT();
        }
        #pragma unroll
        for (int ks = 0; ks < 2; ks++) {
            uint32_t aH[2][4], aL[2][4];
            #pragma unroll
            for (int mt = 0; mt < 2; mt++) {
                ldsm4t(aH[mt], buf + PB_AH + ks * 4352 + at_base + mt * 32);
                ldsm4t(aL[mt], buf + PB_AL + ks * 4352 + at_base + mt * 32);
            }
            #pragma unroll
            for (int ng = 0; ng < 4; ng++) {
                uint32_t bH[4], bL[4];
                uint32_t wrow = (wn * 64 + ng * 16) * 80;
                ldsm4(bH, buf + PB_WH + wrow + wb_base + ks * 32);
                ldsm4(bL, buf + PB_WL + wrow + wb_base + ks * 32);
                #pragma unroll
                for (int mt = 0; mt < 2; mt++) {
                    hmma(s[mt][2 * ng],     aH[mt], bH[0], bH[1]);
                    hmma(s[mt][2 * ng + 1], aH[mt], bH[2], bH[3]);
                    hmma(s[mt][2 * ng],     aH[mt], bL[0], bL[1]);
                    hmma(s[mt][2 * ng + 1], aH[mt], bL[2], bL[3]);
                    hmma(s[mt][2 * ng],     aL[mt], bH[0], bH[1]);
                    hmma(s[mt][2 * ng + 1], aL[mt], bH[2], bH[3]);
                }
            }
        }
    }

    // ---- epilogue: +bias, split, store [bh][n][d] hi/lo ----
    const int o_base = o0 + wn * 64;
    const int head = o_base >> 6;
    const int bhx  = b * 8 + head;
    __nv_bfloat16 *dh = (p == 0) ? g_qh : (p == 1 ? g_kh : g_vh);
    __nv_bfloat16 *dl = (p == 0) ? g_ql : (p == 1 ? g_kl : g_vl);

    float2 bb[8];
    #pragma unroll
    for (int j = 0; j < 8; j++)
        bb[j] = *(const float2 *)&bias[o_base + j * 8 + 2 * (lane & 3)];

    #pragma unroll
    for (int mt = 0; mt < 2; mt++) {
        int r = wm * 32 + mt * 16 + (lane >> 2);
        size_t rowA = ((size_t)bhx * NPIX + m0 + r) * DH;
        size_t rowB = ((size_t)bhx * NPIX + m0 + r + 8) * DH;
        #pragma unroll
        for (int j = 0; j < 8; j++) {
            int d0 = j * 8 + 2 * (lane & 3);
            float y0 = s[mt][j][0] + bb[j].x;
            float y1 = s[mt][j][1] + bb[j].y;
            float y2 = s[mt][j][2] + bb[j].x;
            float y3 = s[mt][j][3] + bb[j].y;
            uint32_t h01 = packbf(y0, y1);
            uint32_t h23 = packbf(y2, y3);
            uint32_t l01 = packbf(y0 - lo_of(h01), y1 - hi_of(h01));
            uint32_t l23 = packbf(y2 - lo_of(h23), y3 - hi_of(h23));
            *(uint32_t *)&dh[rowA + d0] = h01;
            *(uint32_t *)&dl[rowA + d0] = l01;
            *(uint32_t *)&dh[rowB + d0] = h23;
            *(uint32_t *)&dl[rowB + d0] = l23;
        }
    }
}

// ================= HMMA flash attention v2 (unchanged from passing R7) ======
#define SM_AH   0
#define SM_AL   34816
#define BUF0    69632
#define BUF1    122880
#define OB_BH   0
#define OB_BL   17408
#define OB_VH   34816
#define OB_VL   44032
#define SC_OACC 4096
#define SC_OT   40960
#define ATTN_SMEM 176128

__device__ __forceinline__ void stage_bv(uint32_t bufsb, int bh, int j0, int tid) {
    #pragma unroll
    for (int l = 0; l < 4; l++) {
        int c = tid + l * 512;
        int mat = c >> 10, cc = c & 1023;
        int j = cc >> 4, k8 = (cc & 15) * 8;
        const __nv_bfloat16 *s = (k8 < 64)
            ? (mat ? g_kl : g_kh) + ((size_t)bh * NPIX + j0 + j) * DH + k8
            : (mat ? g_ql : g_qh) + ((size_t)bh * NPIX + j0 + j) * DH + (k8 - 64);
        cp16(bufsb + (mat ? OB_BL : OB_BH) + j * 272 + k8 * 2, s);
    }
    #pragma unroll
    for (int l = 0; l < 2; l++) {
        int c = tid + l * 512;
        int mat = c >> 9, cc = c & 511;
        int j = cc >> 3, d8 = (cc & 7) * 8;
        const __nv_bfloat16 *s =
            (mat ? g_vl : g_vh) + ((size_t)bh * NPIX + j0 + j) * DH + d8;
        cp16(bufsb + (mat ? OB_VL : OB_VH) + j * 144 + d8 * 2, s);
    }
}

__global__ __launch_bounds__(512, 1) void attn_kernel(float *__restrict__ out) {
    extern __shared__ __align__(16) char smem[];
    const uint32_t sb = smem_to_u32(smem);

    const int tid  = threadIdx.x;
    const int w    = tid >> 5;
    const int lane = tid & 31;
    const int wm   = w & 7;
    const int wn   = w >> 3;
    const int i0   = blockIdx.x * 128;
    const int bh   = blockIdx.y;
    const int hd   = bh & 7;

    const uint32_t a_off = (lane & 15) * 272 + (lane >> 4) * 16;
    const uint32_t b_off = ((lane >> 4) * 8 + (lane & 7)) * 272 + ((lane >> 3) & 1) * 16;
    const uint32_t v_off = (((lane >> 3) & 1) * 8 + (lane & 7)) * 144 + (lane >> 4) * 16;

    stage_bv(sb + BUF0, bh, 0, tid);
    CP_COMMIT();

    for (int c = tid; c < 4096; c += 512) {
        int mat = c >> 11, cc = c & 2047;
        int i = cc >> 4, k8 = (cc & 15) * 8;
        const __nv_bfloat16 *s = (k8 < 64)
            ? (mat ? g_ql : g_qh) + ((size_t)bh * NPIX + i0 + i) * DH + k8
            : (mat ? g_pl : g_ph) + ((size_t)hd * NPIX + i0 + i) * DH + (k8 - 64);
        *(uint4 *)(smem + (mat ? SM_AL : SM_AH) + i * 272 + k8 * 2) = *(const uint4 *)s;
    }

    float mv[2] = {-1e30f, -1e30f}, lv[2] = {0.f, 0.f};
    float O[8][4];
    #pragma unroll
    for (int c = 0; c < 8; c++)
        #pragma unroll
        for (int e = 0; e < 4; e++) O[c][e] = 0.f;

    for (int kt = 0; kt < 16; kt++) {
        const uint32_t buf = sb + ((kt & 1) ? BUF1 : BUF0);
        CP_WAIT0();
        __syncthreads();
        if (kt < 15) {
            stage_bv(sb + (((kt + 1) & 1) ? BUF1 : BUF0), bh, (kt + 1) * 64, tid);
            CP_COMMIT();
        }

        float s[4][4];
        #pragma unroll
        for (int np = 0; np < 4; np++)
            #pragma unroll
            for (int e = 0; e < 4; e++) s[np][e] = 0.f;
        #pragma unroll
        for (int ks = 0; ks < 8; ks++) {
            uint32_t aH[4], aL[4];
            uint32_t abase = wm * 16 * 272 + ks * 32 + a_off;
            ldsm4(aH, sb + SM_AH + abase);
            ldsm4(aL, sb + SM_AL + abase);
            #pragma unroll
            for (int nt = 0; nt < 2; nt++) {
                uint32_t bH[4], bL[4];
                uint32_t bbase = (wn * 32 + nt * 16) * 272 + ks * 32 + b_off;
                ldsm4(bH, buf + OB_BH + bbase);
                ldsm4(bL, buf + OB_BL + bbase);
                hmma(s[2 * nt],     aH, bH[0], bH[1]);
                hmma(s[2 * nt + 1], aH, bH[2], bH[3]);
                hmma(s[2 * nt],     aH, bL[0], bL[1]);
                hmma(s[2 * nt + 1], aH, bL[2], bL[3]);
                hmma(s[2 * nt],     aL, bH[0], bH[1]);
                hmma(s[2 * nt + 1], aL, bH[2], bH[3]);
            }
        }

        float pm0 = s[0][0], pm1 = s[0][2];
        #pragma unroll
        for (int np = 0; np < 4; np++) {
            pm0 = fmaxf(pm0, fmaxf(s[np][0], s[np][1]));
            pm1 = fmaxf(pm1, fmaxf(s[np][2], s[np][3]));
        }
        pm0 = fmaxf(pm0, __shfl_xor_sync(0xffffffffu, pm0, 1));
        pm0 = fmaxf(pm0, __shfl_xor_sync(0xffffffffu, pm0, 2));
        pm1 = fmaxf(pm1, __shfl_xor_sync(0xffffffffu, pm1, 1));
        pm1 = fmaxf(pm1, __shfl_xor_sync(0xffffffffu, pm1, 2));
        float mn0 = fmaxf(mv[0], pm0), mn1 = fmaxf(mv[1], pm1);
        float sc0 = __expf(mv[0] - mn0), sc1 = __expf(mv[1] - mn1);
        mv[0] = mn0; mv[1] = mn1;
        float sum0 = 0.f, sum1 = 0.f;
        #pragma unroll
        for (int np = 0; np < 4; np++) {
            s[np][0] = __expf(s[np][0] - mn0);
            s[np][1] = __expf(s[np][1] - mn0);
            s[np][2] = __expf(s[np][2] - mn1);
            s[np][3] = __expf(s[np][3] - mn1);
            sum0 += s[np][0] + s[np][1];
            sum1 += s[np][2] + s[np][3];
        }
        sum0 += __shfl_xor_sync(0xffffffffu, sum0, 1);
        sum0 += __shfl_xor_sync(0xffffffffu, sum0, 2);
        sum1 += __shfl_xor_sync(0xffffffffu, sum1, 1);
        sum1 += __shfl_xor_sync(0xffffffffu, sum1, 2);
        lv[0] = lv[0] * sc0 + sum0;
        lv[1] = lv[1] * sc1 + sum1;
        #pragma unroll
        for (int c = 0; c < 8; c++) {
            O[c][0] *= sc0; O[c][1] *= sc0;
            O[c][2] *= sc1; O[c][3] *= sc1;
        }

        uint32_t pH[2][4], pL[2][4];
        #pragma unroll
        for (int kk = 0; kk < 2; kk++) {
            #pragma unroll
            for (int hh = 0; hh < 2; hh++) {
                float e0 = s[2 * kk + hh][0], o0 = s[2 * kk + hh][1];
                float e1 = s[2 * kk + hh][2], o1 = s[2 * kk + hh][3];
                uint32_t h0 = packbf(e0, o0);
                uint32_t h1 = packbf(e1, o1);
                pH[kk][2 * hh]     = h0;
                pH[kk][2 * hh + 1] = h1;
                pL[kk][2 * hh]     = packbf(e0 - lo_of(h0), o0 - hi_of(h0));
                pL[kk][2 * hh + 1] = packbf(e1 - lo_of(h1), o1 - hi_of(h1));
            }
        }

        #pragma unroll
        for (int kk = 0; kk < 2; kk++) {
            uint32_t vrow = (wn * 32 + kk * 16) * 144;
            #pragma unroll
            for (int dp = 0; dp < 4; dp++) {
                uint32_t vH[4], vL[4];
                uint32_t vbase = vrow + dp * 32 + v_off;
                ldsm4t(vH, buf + OB_VH + vbase);
                ldsm4t(vL, buf + OB_VL + vbase);
                hmma(O[2 * dp],     pH[kk], vH[0], vH[1]);
                hmma(O[2 * dp + 1], pH[kk], vH[2], vH[3]);
                hmma(O[2 * dp],     pH[kk], vL[0], vL[1]);
                hmma(O[2 * dp + 1], pH[kk], vL[2], vL[3]);
                hmma(O[2 * dp],     pL[kk], vH[0], vH[1]);
                hmma(O[2 * dp + 1], pL[kk], vH[2], vH[3]);
            }
        }
    }

    __syncthreads();
    float *sm_m = (float *)smem;
    float *sm_l = (float *)(smem + 1024);
    const int r0 = wm * 16 + (lane >> 2);
    sm_m[wn * 128 + r0]     = mv[0];
    sm_m[wn * 128 + r0 + 8] = mv[1];
    sm_l[wn * 128 + r0]     = lv[0];
    sm_l[wn * 128 + r0 + 8] = lv[1];
    __syncthreads();
    float fs[2], lt[2];
    #pragma unroll
    for (int hh = 0; hh < 2; hh++) {
        int rr = r0 + 8 * hh;
        float mo = sm_m[(1 ^ wn) * 128 + rr];
        float lo2 = sm_l[(1 ^ wn) * 128 + rr];
        float mt = fmaxf(mv[hh], mo);
        fs[hh] = __expf(mv[hh] - mt);
        float fo = __expf(mo - mt);
        lt[hh] = lv[hh] * fs[hh] + lo2 * fo;
    }
    float *oacc = (float *)(smem + SC_OACC);
    const int cq = 2 * (lane & 3);
    __syncthreads();
    if (wn == 1) {
        #pragma unroll
        for (int c = 0; c < 8; c++)
            #pragma unroll
            for (int hh = 0; hh < 2; hh++) {
                int rr = r0 + 8 * hh;
                oacc[rr * 68 + 8 * c + cq]     = O[c][2 * hh]     * fs[hh];
                oacc[rr * 68 + 8 * c + cq + 1] = O[c][2 * hh + 1] * fs[hh];
            }
    }
    __syncthreads();
    float *ot = (float *)(smem + SC_OT);
    if (wn == 0) {
        #pragma unroll
        for (int c = 0; c < 8; c++)
            #pragma unroll
            for (int hh = 0; hh < 2; hh++) {
                int rr = r0 + 8 * hh;
                float rlt = 1.0f / lt[hh];
                int d0 = 8 * c + cq;
                ot[d0 * 136 + rr] =
                    (O[c][2 * hh] * fs[hh] + oacc[rr * 68 + d0]) * rlt;
                ot[(d0 + 1) * 136 + rr] =
                    (O[c][2 * hh + 1] * fs[hh] + oacc[rr * 68 + d0 + 1]) * rlt;
            }
    }
    __syncthreads();
    {
        int dr = tid >> 3, ch = (tid & 7) * 16;
        const float *src = ot + dr * 136 + ch;
        float *ob = out + (((size_t)(bh >> 3) * 512) + hd * 64 + dr) * NPIX + i0 + ch;
        #pragma unroll
        for (int e = 0; e < 4; e++)
            *(float4 *)(ob + 4 * e) = *(const float4 *)(src + 4 * e);
    }
}

// ================= launch =================
extern "C" void kernel_launch(void *const *d_in, const int *in_sizes, int n_in,
                              void *d_out, int out_size) {
    const float *x     = (const float *)d_in[0];
    const float *d     = (const float *)d_in[1];
    const float *Wq    = (const float *)d_in[2];
    const float *bq    = (const float *)d_in[3];
    const float *Wk    = (const float *)d_in[4];
    const float *bk    = (const float *)d_in[5];
    const float *Wv    = (const float *)d_in[6];
    const float *bv    = (const float *)d_in[7];
    const float *rel_h = (const float *)d_in[8];
    const float *rel_w = (const float *)d_in[9];
    float *out = (float *)d_out;

    cudaFuncSetAttribute(proj_kernel,
                         cudaFuncAttributeMaxDynamicSharedMemorySize, PROJ_SMEM);
    cudaFuncSetAttribute(attn_kernel,
                         cudaFuncAttributeMaxDynamicSharedMemorySize, ATTN_SMEM);

    split_kernel<<<8960, 256>>>(x, d, Wq, Wk, Wv);
    proj_kernel<<<dim3(32, NB, 3), 256, PROJ_SMEM>>>(bq, bk, bv);
    pos_kernel<<<HEADS * NPIX * DH / 256, 256>>>(rel_h, rel_w);
    attn_kernel<<<dim3(8, NBH), 512, ATTN_SMEM>>>(out);
}

// round 9
// speedup vs baseline: 3.1004x; 1.0208x over previous
#include <cuda_runtime.h>
#include <cuda_bf16.h>
#include <cstdint>

#define HEADS 8
#define DH    64
#define NPIX  1024
#define CC    512
#define NB    8
#define NBH   64
#define XSZ   (NB * CC * NPIX)   // 4194304
#define WSZ   (CC * CC)          // 262144

typedef unsigned long long u64;

// ---- scratch: bf16 hi/lo split operands (allocation-guard-safe globals) ----
__device__ __align__(16) __nv_bfloat16 g_qh[NBH * NPIX * DH];  // [bh][n][d]
__device__ __align__(16) __nv_bfloat16 g_ql[NBH * NPIX * DH];
__device__ __align__(16) __nv_bfloat16 g_kh[NBH * NPIX * DH];
__device__ __align__(16) __nv_bfloat16 g_kl[NBH * NPIX * DH];
__device__ __align__(16) __nv_bfloat16 g_vh[NBH * NPIX * DH];  // [bh][n][d]
__device__ __align__(16) __nv_bfloat16 g_vl[NBH * NPIX * DH];
__device__ __align__(16) __nv_bfloat16 g_ph[HEADS * NPIX * DH]; // [h][n][d]
__device__ __align__(16) __nv_bfloat16 g_pl[HEADS * NPIX * DH];
__device__ __align__(16) __nv_bfloat16 g_xh[XSZ];   // x  [b][c][n]
__device__ __align__(16) __nv_bfloat16 g_xl[XSZ];
__device__ __align__(16) __nv_bfloat16 g_eh[XSZ];   // d  [b][c][n]
__device__ __align__(16) __nv_bfloat16 g_el[XSZ];
__device__ __align__(16) __nv_bfloat16 g_wh[3 * WSZ]; // Wq|Wk|Wv [o][c]
__device__ __align__(16) __nv_bfloat16 g_wl[3 * WSZ];

__device__ __forceinline__ void bsplit(float y, __nv_bfloat16 &hi, __nv_bfloat16 &lo) {
    hi = __float2bfloat16(y);
    lo = __float2bfloat16(y - __bfloat162float(hi));
}

// ---- mma.sync / ldmatrix / cp.async primitives (baseline PTX, sm_80+) ----
__device__ __forceinline__ uint32_t smem_to_u32(const void *p) {
    uint32_t a;
    asm("{ .reg .u64 t; cvta.to.shared.u64 t, %1; cvt.u32.u64 %0, t; }"
        : "=r"(a) : "l"(p));
    return a;
}
__device__ __forceinline__ void ldsm4(uint32_t *r, uint32_t addr) {
    asm volatile("ldmatrix.sync.aligned.m8n8.x4.shared.b16 {%0,%1,%2,%3}, [%4];"
                 : "=r"(r[0]), "=r"(r[1]), "=r"(r[2]), "=r"(r[3]) : "r"(addr));
}
__device__ __forceinline__ void ldsm4t(uint32_t *r, uint32_t addr) {
    asm volatile("ldmatrix.sync.aligned.m8n8.x4.trans.shared.b16 {%0,%1,%2,%3}, [%4];"
                 : "=r"(r[0]), "=r"(r[1]), "=r"(r[2]), "=r"(r[3]) : "r"(addr));
}
__device__ __forceinline__ void hmma(float *c, const uint32_t *a, uint32_t b0, uint32_t b1) {
    asm volatile(
        "mma.sync.aligned.m16n8k16.row.col.f32.bf16.bf16.f32 "
        "{%0,%1,%2,%3}, {%4,%5,%6,%7}, {%8,%9}, {%0,%1,%2,%3};"
        : "+f"(c[0]), "+f"(c[1]), "+f"(c[2]), "+f"(c[3])
        : "r"(a[0]), "r"(a[1]), "r"(a[2]), "r"(a[3]), "r"(b0), "r"(b1));
}
__device__ __forceinline__ void cp16(uint32_t s, const void *g) {
    asm volatile("cp.async.cg.shared.global [%0], [%1], 16;" :: "r"(s), "l"(g));
}
#define CP_COMMIT() asm volatile("cp.async.commit_group;" ::: "memory")
#define CP_WAIT0()  asm volatile("cp.async.wait_group 0;" ::: "memory")

__device__ __forceinline__ uint32_t packbf(float e, float o) {
    uint32_t r;
    asm("cvt.rn.bf16x2.f32 %0, %1, %2;" : "=r"(r) : "f"(o), "f"(e));
    return r;
}
__device__ __forceinline__ float lo_of(uint32_t r) { return __uint_as_float(r << 16); }
__device__ __forceinline__ float hi_of(uint32_t r) { return __uint_as_float(r & 0xFFFF0000u); }

// ================= split inputs/weights to bf16 hi/lo =================
__global__ void split_kernel(const float *__restrict__ x, const float *__restrict__ dsrc,
                             const float *__restrict__ Wq, const float *__restrict__ Wk,
                             const float *__restrict__ Wv) {
    size_t i4 = ((size_t)blockIdx.x * 256 + threadIdx.x) * 4;
    const float *s;
    __nv_bfloat16 *oh, *ol;
    size_t off;
    if (i4 < (size_t)XSZ) {
        s = x; oh = g_xh; ol = g_xl; off = i4;
    } else if (i4 < 2 * (size_t)XSZ) {
        s = dsrc; oh = g_eh; ol = g_el; off = i4 - XSZ;
    } else {
        size_t wi = i4 - 2 * (size_t)XSZ;
        int p = (int)(wi / WSZ);
        off = wi - (size_t)p * WSZ;
        s = (p == 0) ? Wq : (p == 1 ? Wk : Wv);
        oh = g_wh + (size_t)p * WSZ;
        ol = g_wl + (size_t)p * WSZ;
    }
    float4 v = *(const float4 *)&s[off];
    __align__(8) __nv_bfloat16 h[4], l[4];
    bsplit(v.x, h[0], l[0]); bsplit(v.y, h[1], l[1]);
    bsplit(v.z, h[2], l[2]); bsplit(v.w, h[3], l[3]);
    *(u64 *)&oh[off] = *(const u64 *)h;
    *(u64 *)&ol[off] = *(const u64 *)l;
}

// ================= pos = rel_h + rel_w (split) =================
__global__ void pos_kernel(const float *__restrict__ rel_h,
                           const float *__restrict__ rel_w) {
    int idx = blockIdx.x * 256 + threadIdx.x;   // (h*1024+n)*64+d
    int d  = idx & 63;
    int n  = (idx >> 6) & 1023;
    int hh = idx >> 16;
    int w  = n >> 5;
    int hw = n & 31;
    float v = rel_h[(hh * DH + d) * 32 + hw] + rel_w[(hh * DH + d) * 32 + w];
    __nv_bfloat16 bh_, bl_;
    bsplit(v, bh_, bl_);
    g_ph[idx] = bh_;
    g_pl[idx] = bl_;
}

// ================= HMMA projection GEMMs (unchanged from passing R8) ========
#define PB_AH 0
#define PB_AL 8704
#define PB_WH 17408
#define PB_WL 27648
#define PB_SZ 37888
#define PROJ_SMEM (2 * PB_SZ)

__device__ __forceinline__ void stage_proj(uint32_t bufsb,
                                           const __nv_bfloat16 *ah, const __nv_bfloat16 *al,
                                           const __nv_bfloat16 *wh, const __nv_bfloat16 *wl,
                                           int m0, int o0, int k0, int tid) {
    #pragma unroll
    for (int l = 0; l < 2; l++) {
        int c = tid + l * 256;
        int k = c >> 4;
        cp16(bufsb + PB_AH + k * 272 + (c & 15) * 16,
             ah + (size_t)(k0 + k) * NPIX + m0 + (c & 15) * 8);
    }
    #pragma unroll
    for (int l = 0; l < 2; l++) {
        int c = tid + l * 256;
        int k = c >> 4;
        cp16(bufsb + PB_AL + k * 272 + (c & 15) * 16,
             al + (size_t)(k0 + k) * NPIX + m0 + (c & 15) * 8);
    }
    #pragma unroll
    for (int l = 0; l < 2; l++) {
        int c = tid + l * 256;
        int o = c >> 2;
        cp16(bufsb + PB_WH + o * 80 + (c & 3) * 16,
             wh + (size_t)(o0 + o) * CC + k0 + (c & 3) * 8);
    }
    #pragma unroll
    for (int l = 0; l < 2; l++) {
        int c = tid + l * 256;
        int o = c >> 2;
        cp16(bufsb + PB_WL + o * 80 + (c & 3) * 16,
             wl + (size_t)(o0 + o) * CC + k0 + (c & 3) * 8);
    }
}

__global__ __launch_bounds__(256, 2) void proj_kernel(
    const float *__restrict__ bq, const float *__restrict__ bk,
    const float *__restrict__ bv) {
    extern __shared__ __align__(16) char psmem[];
    const uint32_t sb = smem_to_u32(psmem);

    const int p  = blockIdx.z;
    const int b  = blockIdx.y;
    const int m0 = (blockIdx.x >> 2) * 128;
    const int o0 = (blockIdx.x & 3) * 128;

    const int tid  = threadIdx.x;
    const int w    = tid >> 5;
    const int lane = tid & 31;
    const int wm   = w & 3;
    const int wn   = w >> 2;

    const __nv_bfloat16 *ah = ((p == 0) ? g_xh : g_eh) + (size_t)b * CC * NPIX;
    const __nv_bfloat16 *al = ((p == 0) ? g_xl : g_el) + (size_t)b * CC * NPIX;
    const __nv_bfloat16 *wh = g_wh + (size_t)p * WSZ;
    const __nv_bfloat16 *wl = g_wl + (size_t)p * WSZ;
    const float *bias = (p == 0) ? bq : (p == 1 ? bk : bv);

    const uint32_t at_base = (((lane >> 4) * 8) + (lane & 7)) * 272 +
                             wm * 64 + ((lane >> 3) & 1) * 16;
    const uint32_t wb_base = (((lane >> 4) * 8) + (lane & 7)) * 80 +
                             ((lane >> 3) & 1) * 16;

    float s[2][8][4];
    #pragma unroll
    for (int mt = 0; mt < 2; mt++)
        #pragma unroll
        for (int j = 0; j < 8; j++)
            #pragma unroll
            for (int e = 0; e < 4; e++) s[mt][j][e] = 0.f;

    stage_proj(sb, ah, al, wh, wl, m0, o0, 0, tid);
    CP_COMMIT();

    for (int kc = 0; kc < 16; kc++) {
        const uint32_t buf = sb + (kc & 1) * PB_SZ;
        CP_WAIT0();
        __syncthreads();
        if (kc < 15) {
            stage_proj(sb + ((kc + 1) & 1) * PB_SZ, ah, al, wh, wl,
                       m0, o0, (kc + 1) * 32, tid);
            CP_COMMIT();
        }
        #pragma unroll
        for (int ks = 0; ks < 2; ks++) {
            uint32_t aH[2][4], aL[2][4];
            #pragma unroll
            for (int mt = 0; mt < 2; mt++) {
                ldsm4t(aH[mt], buf + PB_AH + ks * 4352 + at_base + mt * 32);
                ldsm4t(aL[mt], buf + PB_AL + ks * 4352 + at_base + mt * 32);
            }
            #pragma unroll
            for (int ng = 0; ng < 4; ng++) {
                uint32_t bH[4], bL[4];
                uint32_t wrow = (wn * 64 + ng * 16) * 80;
                ldsm4(bH, buf + PB_WH + wrow + wb_base + ks * 32);
                ldsm4(bL, buf + PB_WL + wrow + wb_base + ks * 32);
                #pragma unroll
                for (int mt = 0; mt < 2; mt++) {
                    hmma(s[mt][2 * ng],     aH[mt], bH[0], bH[1]);
                    hmma(s[mt][2 * ng + 1], aH[mt], bH[2], bH[3]);
                    hmma(s[mt][2 * ng],     aH[mt], bL[0], bL[1]);
                    hmma(s[mt][2 * ng + 1], aH[mt], bL[2], bL[3]);
                    hmma(s[mt][2 * ng],     aL[mt], bH[0], bH[1]);
                    hmma(s[mt][2 * ng + 1], aL[mt], bH[2], bH[3]);
                }
            }
        }
    }

    const int o_base = o0 + wn * 64;
    const int head = o_base >> 6;
    const int bhx  = b * 8 + head;
    __nv_bfloat16 *dh = (p == 0) ? g_qh : (p == 1 ? g_kh : g_vh);
    __nv_bfloat16 *dl = (p == 0) ? g_ql : (p == 1 ? g_kl : g_vl);

    float2 bb[8];
    #pragma unroll
    for (int j = 0; j < 8; j++)
        bb[j] = *(const float2 *)&bias[o_base + j * 8 + 2 * (lane & 3)];

    #pragma unroll
    for (int mt = 0; mt < 2; mt++) {
        int r = wm * 32 + mt * 16 + (lane >> 2);
        size_t rowA = ((size_t)bhx * NPIX + m0 + r) * DH;
        size_t rowB = ((size_t)bhx * NPIX + m0 + r + 8) * DH;
        #pragma unroll
        for (int j = 0; j < 8; j++) {
            int d0 = j * 8 + 2 * (lane & 3);
            float y0 = s[mt][j][0] + bb[j].x;
            float y1 = s[mt][j][1] + bb[j].y;
            float y2 = s[mt][j][2] + bb[j].x;
            float y3 = s[mt][j][3] + bb[j].y;
            uint32_t h01 = packbf(y0, y1);
            uint32_t h23 = packbf(y2, y3);
            uint32_t l01 = packbf(y0 - lo_of(h01), y1 - hi_of(h01));
            uint32_t l23 = packbf(y2 - lo_of(h23), y3 - hi_of(h23));
            *(uint32_t *)&dh[rowA + d0] = h01;
            *(uint32_t *)&dl[rowA + d0] = l01;
            *(uint32_t *)&dh[rowB + d0] = h23;
            *(uint32_t *)&dl[rowB + d0] = l23;
        }
    }
}

// ================= HMMA flash attention v3: 2 CTAs/SM =================
// 256 threads = 8 warps: wm = w&3 (16-row strip of 64-row i-tile),
// wn = w>>2 (16-col half of 32-col j-tile). Independent flash per half.
// Smem 88,064 B -> 2 CTAs/SM so softmax of one CTA overlaps MMA of the other.
#define SM_AH   0
#define SM_AL   17408
#define BUF0    34816
#define BUF1    61440
#define OB_BH   0
#define OB_BL   8704
#define OB_VH   17408
#define OB_VL   22016
#define SC_OACC 2048
#define SC_OT   20480
#define ATTN_SMEM 88064
// row strides (bytes): A/B = 272, V = 144; OACC 68 f32, OT 72 f32

__device__ __forceinline__ void stage_bv(uint32_t bufsb, int bh, int j0, int tid) {
    #pragma unroll
    for (int l = 0; l < 4; l++) {
        int c = tid + l * 256;              // 0..1023: B hi/lo (32 rows x 128 k)
        int mat = c >> 9, cc = c & 511;
        int j = cc >> 4, k8 = (cc & 15) * 8;
        const __nv_bfloat16 *s = (k8 < 64)
            ? (mat ? g_kl : g_kh) + ((size_t)bh * NPIX + j0 + j) * DH + k8
            : (mat ? g_ql : g_qh) + ((size_t)bh * NPIX + j0 + j) * DH + (k8 - 64);
        cp16(bufsb + (mat ? OB_BL : OB_BH) + j * 272 + k8 * 2, s);
    }
    #pragma unroll
    for (int l = 0; l < 2; l++) {
        int c = tid + l * 256;              // 0..511: V hi/lo (32 rows x 64 d)
        int mat = c >> 8, cc = c & 255;
        int j = cc >> 3, d8 = (cc & 7) * 8;
        const __nv_bfloat16 *s =
            (mat ? g_vl : g_vh) + ((size_t)bh * NPIX + j0 + j) * DH + d8;
        cp16(bufsb + (mat ? OB_VL : OB_VH) + j * 144 + d8 * 2, s);
    }
}

__global__ __launch_bounds__(256, 2) void attn_kernel(float *__restrict__ out) {
    extern __shared__ __align__(16) char smem[];
    const uint32_t sb = smem_to_u32(smem);

    const int tid  = threadIdx.x;
    const int w    = tid >> 5;
    const int lane = tid & 31;
    const int wm   = w & 3;
    const int wn   = w >> 2;
    const int i0   = blockIdx.x * 64;
    const int bh   = blockIdx.y;
    const int hd   = bh & 7;

    const uint32_t a_off = (lane & 15) * 272 + (lane >> 4) * 16;
    const uint32_t b_off = ((lane >> 4) * 8 + (lane & 7)) * 272 + ((lane >> 3) & 1) * 16;
    const uint32_t v_off = (((lane >> 3) & 1) * 8 + (lane & 7)) * 144 + (lane >> 4) * 16;

    stage_bv(sb + BUF0, bh, 0, tid);
    CP_COMMIT();

    // stage A = [q_i | pos_i] hi/lo (64 rows, once)
    for (int c = tid; c < 2048; c += 256) {
        int mat = c >> 10, cc = c & 1023;
        int i = cc >> 4, k8 = (cc & 15) * 8;
        const __nv_bfloat16 *s = (k8 < 64)
            ? (mat ? g_ql : g_qh) + ((size_t)bh * NPIX + i0 + i) * DH + k8
            : (mat ? g_pl : g_ph) + ((size_t)hd * NPIX + i0 + i) * DH + (k8 - 64);
        *(uint4 *)(smem + (mat ? SM_AL : SM_AH) + i * 272 + k8 * 2) = *(const uint4 *)s;
    }

    float mv[2] = {-1e30f, -1e30f}, lv[2] = {0.f, 0.f};
    float O[8][4];
    #pragma unroll
    for (int c = 0; c < 8; c++)
        #pragma unroll
        for (int e = 0; e < 4; e++) O[c][e] = 0.f;

    for (int kt = 0; kt < 32; kt++) {
        const uint32_t buf = sb + ((kt & 1) ? BUF1 : BUF0);
        CP_WAIT0();
        __syncthreads();
        if (kt < 31) {
            stage_bv(sb + (((kt + 1) & 1) ? BUF1 : BUF0), bh, (kt + 1) * 32, tid);
            CP_COMMIT();
        }

        // ---- S = A·B^T (16 rows x 16 cols per warp, k=128, 3 splits) ----
        float s[2][4];
        #pragma unroll
        for (int nt = 0; nt < 2; nt++)
            #pragma unroll
            for (int e = 0; e < 4; e++) s[nt][e] = 0.f;
        #pragma unroll
        for (int ks = 0; ks < 8; ks++) {
            uint32_t aH[4], aL[4];
            uint32_t abase = wm * 16 * 272 + ks * 32 + a_off;
            ldsm4(aH, sb + SM_AH + abase);
            ldsm4(aL, sb + SM_AL + abase);
            uint32_t bH[4], bL[4];
            uint32_t bbase = wn * 16 * 272 + ks * 32 + b_off;
            ldsm4(bH, buf + OB_BH + bbase);
            ldsm4(bL, buf + OB_BL + bbase);
            hmma(s[0], aH, bH[0], bH[1]);
            hmma(s[1], aH, bH[2], bH[3]);
            hmma(s[0], aH, bL[0], bL[1]);
            hmma(s[1], aH, bL[2], bL[3]);
            hmma(s[0], aL, bH[0], bH[1]);
            hmma(s[1], aL, bH[2], bH[3]);
        }

        // ---- warp-local online softmax over own 16 cols ----
        float pm0 = fmaxf(fmaxf(s[0][0], s[0][1]), fmaxf(s[1][0], s[1][1]));
        float pm1 = fmaxf(fmaxf(s[0][2], s[0][3]), fmaxf(s[1][2], s[1][3]));
        pm0 = fmaxf(pm0, __shfl_xor_sync(0xffffffffu, pm0, 1));
        pm0 = fmaxf(pm0, __shfl_xor_sync(0xffffffffu, pm0, 2));
        pm1 = fmaxf(pm1, __shfl_xor_sync(0xffffffffu, pm1, 1));
        pm1 = fmaxf(pm1, __shfl_xor_sync(0xffffffffu, pm1, 2));
        float mn0 = fmaxf(mv[0], pm0), mn1 = fmaxf(mv[1], pm1);
        float sc0 = __expf(mv[0] - mn0), sc1 = __expf(mv[1] - mn1);
        mv[0] = mn0; mv[1] = mn1;
        float sum0 = 0.f, sum1 = 0.f;
        #pragma unroll
        for (int nt = 0; nt < 2; nt++) {
            s[nt][0] = __expf(s[nt][0] - mn0);
            s[nt][1] = __expf(s[nt][1] - mn0);
            s[nt][2] = __expf(s[nt][2] - mn1);
            s[nt][3] = __expf(s[nt][3] - mn1);
            sum0 += s[nt][0] + s[nt][1];
            sum1 += s[nt][2] + s[nt][3];
        }
        sum0 += __shfl_xor_sync(0xffffffffu, sum0, 1);
        sum0 += __shfl_xor_sync(0xffffffffu, sum0, 2);
        sum1 += __shfl_xor_sync(0xffffffffu, sum1, 1);
        sum1 += __shfl_xor_sync(0xffffffffu, sum1, 2);
        lv[0] = lv[0] * sc0 + sum0;
        lv[1] = lv[1] * sc1 + sum1;
        #pragma unroll
        for (int c = 0; c < 8; c++) {
            O[c][0] *= sc0; O[c][1] *= sc0;
            O[c][2] *= sc1; O[c][3] *= sc1;
        }

        // ---- P fragments from acc regs (hi/lo split) ----
        uint32_t pH[4], pL[4];
        #pragma unroll
        for (int hh = 0; hh < 2; hh++) {
            float e0 = s[hh][0], o0 = s[hh][1];
            float e1 = s[hh][2], o1 = s[hh][3];
            uint32_t h0 = packbf(e0, o0);
            uint32_t h1 = packbf(e1, o1);
            pH[2 * hh]     = h0;
            pH[2 * hh + 1] = h1;
            pL[2 * hh]     = packbf(e0 - lo_of(h0), o0 - hi_of(h0));
            pL[2 * hh + 1] = packbf(e1 - lo_of(h1), o1 - hi_of(h1));
        }

        // ---- O += P·V over own 16 j (k=16, 3 splits) ----
        {
            uint32_t vrow = wn * 16 * 144;
            #pragma unroll
            for (int dp = 0; dp < 4; dp++) {
                uint32_t vH[4], vL[4];
                uint32_t vbase = vrow + dp * 32 + v_off;
                ldsm4t(vH, buf + OB_VH + vbase);
                ldsm4t(vL, buf + OB_VL + vbase);
                hmma(O[2 * dp],     pH, vH[0], vH[1]);
                hmma(O[2 * dp + 1], pH, vH[2], vH[3]);
                hmma(O[2 * dp],     pH, vL[0], vL[1]);
                hmma(O[2 * dp + 1], pH, vL[2], vL[3]);
                hmma(O[2 * dp],     pL, vH[0], vH[1]);
                hmma(O[2 * dp + 1], pL, vH[2], vH[3]);
            }
        }
    }

    // ---- epilogue: merge the two column-halves, normalize, store ----
    __syncthreads();
    float *sm_m = (float *)smem;           // [2][64]
    float *sm_l = (float *)(smem + 512);   // [2][64]
    const int r0 = wm * 16 + (lane >> 2);
    sm_m[wn * 64 + r0]     = mv[0];
    sm_m[wn * 64 + r0 + 8] = mv[1];
    sm_l[wn * 64 + r0]     = lv[0];
    sm_l[wn * 64 + r0 + 8] = lv[1];
    __syncthreads();
    float fs[2], lt[2];
    #pragma unroll
    for (int hh = 0; hh < 2; hh++) {
        int rr = r0 + 8 * hh;
        float mo = sm_m[(1 ^ wn) * 64 + rr];
        float lo2 = sm_l[(1 ^ wn) * 64 + rr];
        float mt = fmaxf(mv[hh], mo);
        fs[hh] = __expf(mv[hh] - mt);
        float fo = __expf(mo - mt);
        lt[hh] = lv[hh] * fs[hh] + lo2 * fo;
    }
    float *oacc = (float *)(smem + SC_OACC);   // [64][68]
    const int cq = 2 * (lane & 3);
    __syncthreads();
    if (wn == 1) {
        #pragma unroll
        for (int c = 0; c < 8; c++)
            #pragma unroll
            for (int hh = 0; hh < 2; hh++) {
                int rr = r0 + 8 * hh;
                oacc[rr * 68 + 8 * c + cq]     = O[c][2 * hh]     * fs[hh];
                oacc[rr * 68 + 8 * c + cq + 1] = O[c][2 * hh + 1] * fs[hh];
            }
    }
    __syncthreads();
    float *ot = (float *)(smem + SC_OT);       // [64 d][72]
    if (wn == 0) {
        #pragma unroll
        for (int c = 0; c < 8; c++)
            #pragma unroll
            for (int hh = 0; hh < 2; hh++) {
                int rr = r0 + 8 * hh;
                float rlt = 1.0f / lt[hh];
                int d0 = 8 * c + cq;
                ot[d0 * 72 + rr] =
                    (O[c][2 * hh] * fs[hh] + oacc[rr * 68 + d0]) * rlt;
                ot[(d0 + 1) * 72 + rr] =
                    (O[c][2 * hh + 1] * fs[hh] + oacc[rr * 68 + d0 + 1]) * rlt;
            }
    }
    __syncthreads();
    {
        int dr = tid >> 2, ch = (tid & 3) * 16;
        const float *src = ot + dr * 72 + ch;
        float *ob = out + (((size_t)(bh >> 3) * 512) + hd * 64 + dr) * NPIX + i0 + ch;
        #pragma unroll
        for (int e = 0; e < 4; e++)
            *(float4 *)(ob + 4 * e) = *(const float4 *)(src + 4 * e);
    }
}

// ================= launch =================
extern "C" void kernel_launch(void *const *d_in, const int *in_sizes, int n_in,
                              void *d_out, int out_size) {
    const float *x     = (const float *)d_in[0];
    const float *d     = (const float *)d_in[1];
    const float *Wq    = (const float *)d_in[2];
    const float *bq    = (const float *)d_in[3];
    const float *Wk    = (const float *)d_in[4];
    const float *bk    = (const float *)d_in[5];
    const float *Wv    = (const float *)d_in[6];
    const float *bv    = (const float *)d_in[7];
    const float *rel_h = (const float *)d_in[8];
    const float *rel_w = (const float *)d_in[9];
    float *out = (float *)d_out;

    cudaFuncSetAttribute(proj_kernel,
                         cudaFuncAttributeMaxDynamicSharedMemorySize, PROJ_SMEM);
    cudaFuncSetAttribute(attn_kernel,
                         cudaFuncAttributeMaxDynamicSharedMemorySize, ATTN_SMEM);

    split_kernel<<<8960, 256>>>(x, d, Wq, Wk, Wv);
    proj_kernel<<<dim3(32, NB, 3), 256, PROJ_SMEM>>>(bq, bk, bv);
    pos_kernel<<<HEADS * NPIX * DH / 256, 256>>>(rel_h, rel_w);
    attn_kernel<<<dim3(16, NBH), 256, ATTN_SMEM>>>(out);
}